// round 3
// baseline (speedup 1.0000x reference)
#include <cuda_runtime.h>
#include <cuda_bf16.h>

// Fused DCNv2 forward:
//   ow   = conv3x3(x; w_off, b_off)            -> 27 channels per pixel
//   off  = ow[0:18]  (K=9 points, (y,x) pairs)
//   mask = sigmoid(ow[18:27])
//   out[o] = b_def[o] + sum_{c,k} w_def[o,c,k] * bilinear(x[c], p_k) * mask[k]
//
// Shapes: x (8,3,512,512) f32, w_off (27,3,3,3), b_off (27),
//         w_def (3,3,3,3), b_def (3), out (8,3,512,512) f32.

#define HH 512
#define WW 512
#define CC 3
#define OCC 27
#define KK 9

__global__ __launch_bounds__(256)
void dcn_fused_kernel(const float* __restrict__ x,
                      const float* __restrict__ w_off,
                      const float* __restrict__ b_off,
                      const float* __restrict__ w_def,
                      const float* __restrict__ b_def,
                      float* __restrict__ out,
                      int total)
{
    // Stage all weights in shared memory (broadcast reads: conflict-free).
    __shared__ float s_woff[OCC * 27];  // [oc][c*9 + ky*3 + kx]
    __shared__ float s_wdef[3 * 27];    // [o][c*9 + k]
    __shared__ float s_boff[OCC];
    __shared__ float s_bdef[3];

    for (int i = threadIdx.x; i < OCC * 27; i += blockDim.x) s_woff[i] = w_off[i];
    for (int i = threadIdx.x; i < 3 * 27;  i += blockDim.x) s_wdef[i] = w_def[i];
    if (threadIdx.x < OCC) s_boff[threadIdx.x] = b_off[threadIdx.x];
    if (threadIdx.x < 3)   s_bdef[threadIdx.x] = b_def[threadIdx.x];
    __syncthreads();

    int idx = blockIdx.x * blockDim.x + threadIdx.x;
    if (idx >= total) return;

    const int wI = idx & (WW - 1);
    const int hI = (idx >> 9) & (HH - 1);
    const int b  = idx >> 18;

    const float* xb = x + (size_t)b * CC * HH * WW;

    // ---- 3x3x3 neighborhood (zero padding) ----
    float xn[CC][9];
#pragma unroll
    for (int c = 0; c < CC; ++c) {
        const float* xc = xb + c * HH * WW;
#pragma unroll
        for (int ky = 0; ky < 3; ++ky) {
            const int y = hI + ky - 1;
            const bool yv = ((unsigned)y < (unsigned)HH);
#pragma unroll
            for (int kx = 0; kx < 3; ++kx) {
                const int xx = wI + kx - 1;
                const bool v = yv && ((unsigned)xx < (unsigned)WW);
                xn[c][ky * 3 + kx] = v ? __ldg(xc + y * WW + xx) : 0.0f;
            }
        }
    }

    // ---- offset/mask conv: 27 outputs, 729 FMAs ----
    float ow[OCC];
#pragma unroll
    for (int oc = 0; oc < OCC; ++oc) ow[oc] = s_boff[oc];

#pragma unroll
    for (int c = 0; c < CC; ++c) {
#pragma unroll
        for (int t = 0; t < 9; ++t) {
            const float v = xn[c][t];
#pragma unroll
            for (int oc = 0; oc < OCC; ++oc)
                ow[oc] = fmaf(s_woff[oc * 27 + c * 9 + t], v, ow[oc]);
        }
    }

    // ---- deformable sampling + channel mix ----
    float acc0 = s_bdef[0];
    float acc1 = s_bdef[1];
    float acc2 = s_bdef[2];

#pragma unroll
    for (int k = 0; k < KK; ++k) {
        const float py = (float)hI + (float)(k / 3 - 1) + ow[2 * k];
        const float px = (float)wI + (float)(k % 3 - 1) + ow[2 * k + 1];
        const float m  = 1.0f / (1.0f + __expf(-ow[18 + k]));

        const float y0f = floorf(py);
        const float x0f = floorf(px);
        const float dy = py - y0f;
        const float dx = px - x0f;
        const int y0  = (int)y0f;
        const int x0i = (int)x0f;

        const float w00 = (1.0f - dy) * (1.0f - dx);
        const float w01 = (1.0f - dy) * dx;
        const float w10 = dy * (1.0f - dx);
        const float w11 = dy * dx;

        const bool y0v = ((unsigned)y0        < (unsigned)HH);
        const bool y1v = ((unsigned)(y0 + 1)  < (unsigned)HH);
        const bool x0v = ((unsigned)x0i       < (unsigned)WW);
        const bool x1v = ((unsigned)(x0i + 1) < (unsigned)WW);
        const int i00 = y0 * WW + x0i;

#pragma unroll
        for (int c = 0; c < CC; ++c) {
            const float* pc = xb + c * HH * WW;
            const float v00 = (y0v && x0v) ? __ldg(pc + i00)          : 0.0f;
            const float v01 = (y0v && x1v) ? __ldg(pc + i00 + 1)      : 0.0f;
            const float v10 = (y1v && x0v) ? __ldg(pc + i00 + WW)     : 0.0f;
            const float v11 = (y1v && x1v) ? __ldg(pc + i00 + WW + 1) : 0.0f;

            const float val = (v00 * w00 + v01 * w01 + v10 * w10 + v11 * w11) * m;

            acc0 = fmaf(s_wdef[0 * 27 + c * 9 + k], val, acc0);
            acc1 = fmaf(s_wdef[1 * 27 + c * 9 + k], val, acc1);
            acc2 = fmaf(s_wdef[2 * 27 + c * 9 + k], val, acc2);
        }
    }

    const size_t obase = (size_t)b * 3 * HH * WW + (size_t)hI * WW + wI;
    out[obase]               = acc0;
    out[obase + HH * WW]     = acc1;
    out[obase + 2 * HH * WW] = acc2;
}

extern "C" void kernel_launch(void* const* d_in, const int* in_sizes, int n_in,
                              void* d_out, int out_size)
{
    const float* x     = (const float*)d_in[0];
    const float* w_off = (const float*)d_in[1];
    const float* b_off = (const float*)d_in[2];
    const float* w_def = (const float*)d_in[3];
    const float* b_def = (const float*)d_in[4];
    float* out = (float*)d_out;

    const int total = 8 * 512 * 512;  // B * H * W pixels (3 output ch per pixel)
    const int threads = 256;
    const int blocks = (total + threads - 1) / threads;

    dcn_fused_kernel<<<blocks, threads>>>(x, w_off, b_off, w_def, b_def, out, total);
}

// round 4
// speedup vs baseline: 1.3397x; 1.3397x over previous
#include <cuda_runtime.h>
#include <cuda_bf16.h>

// Fused DCNv2 forward, 2 pixels/thread with packed f32x2 math.
//   ow   = conv3x3(x; w_off, b_off)            -> 27 channels per pixel
//   off  = ow[0:18]  (K=9 points, (y,x) pairs)
//   mask = sigmoid(ow[18:27])
//   out[o] = b_def[o] + sum_{c,k} w_def[o,c,k] * bilinear(x[c], p_k) * mask[k]
//
// x (8,3,512,512) f32, w_off (27,3,3,3), b_off (27), w_def (3,3,3,3), b_def (3).

#define HH 512
#define WW 512
#define CC 3
#define OCC 27
#define OCP 28          // padded to even for LDS.128 pairs
#define KK 9
#define HW (HH * WW)

typedef unsigned long long u64;

__device__ __forceinline__ u64 pk2(float lo, float hi) {
    u64 r; asm("mov.b64 %0, {%1, %2};" : "=l"(r) : "f"(lo), "f"(hi)); return r;
}
__device__ __forceinline__ void upk2(u64 v, float& lo, float& hi) {
    asm("mov.b64 {%0, %1}, %2;" : "=f"(lo), "=f"(hi) : "l"(v));
}
__device__ __forceinline__ void ffma2(u64& acc, u64 a, u64 b) {
    asm("fma.rn.f32x2 %0, %1, %2, %0;" : "+l"(acc) : "l"(a), "l"(b));
}

__global__ __launch_bounds__(128)
void dcn_fused2_kernel(const float* __restrict__ x,
                       const float* __restrict__ w_off,
                       const float* __restrict__ b_off,
                       const float* __restrict__ w_def,
                       const float* __restrict__ b_def,
                       float* __restrict__ out)
{
    // Duplicated + transposed conv weights: s_wd[g*OCP + oc] = {w[oc][g], w[oc][g]},
    // g = c*9 + ky*3 + kx. Padded oc=27 entry is zero. 16B-aligned for LDS.128.
    __shared__ __align__(16) u64 s_wd[OCC * OCP];   // 756 * 8B
    __shared__ u64 s_wdd[3 * 27];                   // duplicated w_def
    __shared__ float s_boff[OCC];
    __shared__ float s_bdef[3];

    for (int i = threadIdx.x; i < OCC * OCP; i += blockDim.x) {
        const int g = i / OCP, oc = i % OCP;
        const float w = (oc < OCC) ? w_off[oc * 27 + g] : 0.0f;
        s_wd[i] = pk2(w, w);
    }
    for (int i = threadIdx.x; i < 3 * 27; i += blockDim.x) {
        const float w = w_def[i];
        s_wdd[i] = pk2(w, w);
    }
    if (threadIdx.x < OCC) s_boff[threadIdx.x] = b_off[threadIdx.x];
    if (threadIdx.x < 3)   s_bdef[threadIdx.x] = b_def[threadIdx.x];
    __syncthreads();

    // One thread = pixel pair (hI, wI) and (hI, wI+1), wI even.
    const int idx = blockIdx.x * blockDim.x + threadIdx.x;   // 0 .. 8*512*256-1
    const int wI = (idx & 255) << 1;
    const int hI = (idx >> 8) & (HH - 1);
    const int b  = idx >> 17;

    const float* xb = x + (size_t)b * CC * HW;

    // ---- offset/mask conv on both pixels (packed) ----
    u64 ow[OCP];
#pragma unroll
    for (int oc = 0; oc < OCC; ++oc) ow[oc] = pk2(s_boff[oc], s_boff[oc]);
    ow[27] = 0ull;

#pragma unroll
    for (int c = 0; c < CC; ++c) {
        const float* xc = xb + c * HW;
        // 3x4 window covering both pixels' 3x3 neighborhoods (zero padded)
        float win[12];
#pragma unroll
        for (int r = 0; r < 3; ++r) {
            const int y = hI + r - 1;
            const bool yv = ((unsigned)y < (unsigned)HH);
#pragma unroll
            for (int j = 0; j < 4; ++j) {
                const int xx = wI + j - 1;
                const bool v = yv && ((unsigned)xx < (unsigned)WW);
                win[r * 4 + j] = v ? __ldg(xc + y * WW + xx) : 0.0f;
            }
        }
#pragma unroll
        for (int t = 0; t < 9; ++t) {
            const int ky = t / 3, kx = t % 3;
            const u64 v2 = pk2(win[ky * 4 + kx], win[ky * 4 + kx + 1]);
            const ulonglong2* wrow =
                reinterpret_cast<const ulonglong2*>(&s_wd[(c * 9 + t) * OCP]);
#pragma unroll
            for (int i = 0; i < OCP / 2; ++i) {      // 14 x LDS.128
                const ulonglong2 wv = wrow[i];
                ffma2(ow[2 * i],     wv.x, v2);
                ffma2(ow[2 * i + 1], wv.y, v2);
            }
        }
    }

    // ---- deformable sampling + channel mix (acc packed across the 2 pixels) ----
    u64 acc[3];
#pragma unroll
    for (int o = 0; o < 3; ++o) acc[o] = pk2(s_bdef[o], s_bdef[o]);

#pragma unroll
    for (int k = 0; k < KK; ++k) {
        float oy0, oy1, ox0, ox1, z0, z1;
        upk2(ow[2 * k],     oy0, oy1);
        upk2(ow[2 * k + 1], ox0, ox1);
        upk2(ow[18 + k],    z0,  z1);
        const float m0 = 1.0f / (1.0f + __expf(-z0));
        const float m1 = 1.0f / (1.0f + __expf(-z1));

        const float kyf = (float)(k / 3 - 1);
        const float kxf = (float)(k % 3 - 1);

        // per-pixel sample geometry
        float w00[2], w01[2], w10[2], w11[2];
        int   i00[2];
        bool  y0v[2], y1v[2], x0v[2], x1v[2];
#pragma unroll
        for (int p = 0; p < 2; ++p) {
            const float py = (float)hI + kyf + (p ? oy1 : oy0);
            const float px = (float)(wI + p) + kxf + (p ? ox1 : ox0);
            const float y0f = floorf(py);
            const float x0f = floorf(px);
            const float dy = py - y0f;
            const float dx = px - x0f;
            const int y0 = (int)y0f;
            const int x0 = (int)x0f;
            w00[p] = (1.0f - dy) * (1.0f - dx);
            w01[p] = (1.0f - dy) * dx;
            w10[p] = dy * (1.0f - dx);
            w11[p] = dy * dx;
            y0v[p] = ((unsigned)y0       < (unsigned)HH);
            y1v[p] = ((unsigned)(y0 + 1) < (unsigned)HH);
            x0v[p] = ((unsigned)x0       < (unsigned)WW);
            x1v[p] = ((unsigned)(x0 + 1) < (unsigned)WW);
            i00[p] = y0 * WW + x0;
        }

#pragma unroll
        for (int c = 0; c < CC; ++c) {
            const float* pc = xb + c * HW;
            float val[2];
#pragma unroll
            for (int p = 0; p < 2; ++p) {
                const float v00 = (y0v[p] && x0v[p]) ? __ldg(pc + i00[p])          : 0.0f;
                const float v01 = (y0v[p] && x1v[p]) ? __ldg(pc + i00[p] + 1)      : 0.0f;
                const float v10 = (y1v[p] && x0v[p]) ? __ldg(pc + i00[p] + WW)     : 0.0f;
                const float v11 = (y1v[p] && x1v[p]) ? __ldg(pc + i00[p] + WW + 1) : 0.0f;
                val[p] = v00 * w00[p] + v01 * w01[p] + v10 * w10[p] + v11 * w11[p];
            }
            const u64 vp = pk2(val[0] * m0, val[1] * m1);
#pragma unroll
            for (int o = 0; o < 3; ++o)
                ffma2(acc[o], s_wdd[o * 27 + c * 9 + k], vp);
        }
    }

    const size_t obase = (size_t)b * 3 * HW + (size_t)hI * WW + wI;
#pragma unroll
    for (int o = 0; o < 3; ++o) {
        float lo, hi; upk2(acc[o], lo, hi);
        *reinterpret_cast<float2*>(out + obase + (size_t)o * HW) = make_float2(lo, hi);
    }
}

extern "C" void kernel_launch(void* const* d_in, const int* in_sizes, int n_in,
                              void* d_out, int out_size)
{
    const float* x     = (const float*)d_in[0];
    const float* w_off = (const float*)d_in[1];
    const float* b_off = (const float*)d_in[2];
    const float* w_def = (const float*)d_in[3];
    const float* b_def = (const float*)d_in[4];
    float* out = (float*)d_out;

    const int totalPairs = 8 * 512 * 256;   // 1,048,576 pixel pairs
    const int threads = 128;
    const int blocks = totalPairs / threads; // 8192

    dcn_fused2_kernel<<<blocks, threads>>>(x, w_off, b_off, w_def, b_def, out);
}